// round 9
// baseline (speedup 1.0000x reference)
#include <cuda_runtime.h>
#include <cstdint>

constexpr int TOK = 32, DMODEL = 256, HEADS = 8, INNER = 512;
constexpr int GROUPS = 4096, NQKV = 1536, DHEAD = 64;
constexpr int NG = 2, MR = 64;        // groups / rows per block
constexpr int NT_THREADS = 512;       // 16 warps

// ---- smem plan (float offsets); A-side strides %32==4, B-side %32==8 ----
constexpr int XS_STR = 260, XS_OFF = 0;                    // x tf32 [64][256]
constexpr int WS_OFF = XS_OFF + MR * XS_STR;               // W ring: 3 slots x 3200
constexpr int WS_STR = 200;                                //   B1 chunk [16k][192]
constexpr int WO_STR = 264;                                //   B3 chunk [8k][256]
constexpr int WSLOT  = 3200;
constexpr int PS_STR = 36,  PS_OFF = WS_OFF + 2 * WSLOT;   // P [64][36] (alias slot2)
constexpr int QS_STR = 68,  QS_OFF = WS_OFF + 3 * WSLOT;   // Q tf32 [64][64]
constexpr int KS_STR = 68,  KS_OFF = QS_OFF + MR * QS_STR;
constexpr int VS_STR = 72,  VS_OFF = KS_OFF + MR * KS_STR;
constexpr int AS_STR = 68,  AS_OFF = VS_OFF + MR * VS_STR;
constexpr int SM_FLOATS = AS_OFF + MR * AS_STR;
constexpr int SM_BYTES  = SM_FLOATS * 4;                   // ~171.5 KB -> 1 block/SM

__device__ __forceinline__ float ftf(float f) {
    uint32_t u; asm("cvt.rna.tf32.f32 %0, %1;" : "=r"(u) : "f"(f));
    return __uint_as_float(u);
}
__device__ __forceinline__ uint32_t ftfu(float f) {
    uint32_t u; asm("cvt.rna.tf32.f32 %0, %1;" : "=r"(u) : "f"(f));
    return u;
}
__device__ __forceinline__ void mma8(float* d, const uint32_t* a, const uint32_t* b) {
    asm volatile("mma.sync.aligned.m16n8k8.row.col.f32.tf32.tf32.f32 "
                 "{%0,%1,%2,%3},{%4,%5,%6,%7},{%8,%9},{%0,%1,%2,%3};"
                 : "+f"(d[0]), "+f"(d[1]), "+f"(d[2]), "+f"(d[3])
                 : "r"(a[0]), "r"(a[1]), "r"(a[2]), "r"(a[3]), "r"(b[0]), "r"(b[1]));
}
__device__ __forceinline__ void ldsm4(uint32_t* r, uint32_t saddr) {
    asm volatile("ldmatrix.sync.aligned.m8n8.x4.shared.b16 {%0,%1,%2,%3}, [%4];"
                 : "=r"(r[0]), "=r"(r[1]), "=r"(r[2]), "=r"(r[3]) : "r"(saddr));
}
__device__ __forceinline__ void cpa16(uint32_t dst, const void* src) {
    asm volatile("cp.async.ca.shared.global [%0], [%1], 16;" :: "r"(dst), "l"(src));
}
__device__ __forceinline__ void cp_commit() { asm volatile("cp.async.commit_group;"); }
template<int N> __device__ __forceinline__ void cp_wait() {
    asm volatile("cp.async.wait_group %0;" :: "n"(N));
}

__global__ __launch_bounds__(NT_THREADS, 1)
void fused_attn_kernel(const float* __restrict__ x,
                       const float* __restrict__ Wqkv,
                       const float* __restrict__ Wout,
                       const float* __restrict__ bout,
                       float* __restrict__ out)
{
    extern __shared__ float sm[];
    const int tid = threadIdx.x;
    const int blk = blockIdx.x;          // rows blk*64 .. +63
    const int w   = tid >> 5;            // 0..15
    const int ln  = tid & 31;
    const int g4  = ln >> 2;
    const int t4  = ln & 3;
    const int wm  = w >> 3;              // M-half 0/1 (B1, B3)
    const int wn  = w & 7;               // col group

    const uint32_t sb = (uint32_t)__cvta_generic_to_shared(sm);
    const int lrow = ln & 15, lcol4 = (ln >> 4) * 4;
    const uint32_t xs_lds = sb + ((XS_OFF + (wm * 32 + lrow) * XS_STR + lcol4) << 2);
    const uint32_t qs_lds = sb + ((QS_OFF + ((w >> 3) * 32 + ((w >> 2) & 1) * 16 + lrow) * QS_STR + lcol4) << 2);
    const uint32_t ps_lds = sb + ((PS_OFF + ((w >> 3) * 32 + lrow) * PS_STR + lcol4) << 2);
    const uint32_t as_lds = sb + ((AS_OFF + (wm * 32 + lrow) * AS_STR + lcol4) << 2);

    // staging indices: B1 chunk = 768 float4 (512 + 256 threads)
    const int wkk0 = tid / 48,         wcol0 = (tid % 48) * 4;
    const int wkk1 = (512 + tid) / 48, wcol1 = ((512 + tid) % 48) * 4;
    // B3 chunk = 512 float4
    const int odd8 = tid >> 6, oc4 = (tid & 63) * 4;

    auto issueW = [&](int h, int c, int p) {
        const int kc = c * 16;
        {
            const int sec = wcol0 >> 6, dd = wcol0 & 63;
            cpa16(sb + ((WS_OFF + p * WSLOT + wkk0 * WS_STR + wcol0) << 2),
                  Wqkv + (size_t)(kc + wkk0) * NQKV + sec * INNER + h * DHEAD + dd);
        }
        if (tid < 256) {
            const int sec = wcol1 >> 6, dd = wcol1 & 63;
            cpa16(sb + ((WS_OFF + p * WSLOT + wkk1 * WS_STR + wcol1) << 2),
                  Wqkv + (size_t)(kc + wkk1) * NQKV + sec * INNER + h * DHEAD + dd);
        }
        cp_commit();
    };
    auto issueWO = [&](int h, int c, int p) {
        cpa16(sb + ((WS_OFF + p * WSLOT + odd8 * WO_STR + oc4) << 2),
              Wout + (size_t)(h * DHEAD + c * 8 + odd8) * DMODEL + oc4);
        cp_commit();
    };

    issueW(0, 0, 0); issueW(0, 1, 1);

    // stage x[64][256] tf32
    {
        const float4* xg = reinterpret_cast<const float4*>(x + (size_t)blk * MR * DMODEL);
        #pragma unroll
        for (int it = 0; it < 8; it++) {
            int l = tid + it * 512;
            int row = l >> 6, c4 = l & 63;
            float4 v = xg[l];
            *reinterpret_cast<float4*>(sm + XS_OFF + row * XS_STR + c4 * 4) =
                make_float4(ftf(v.x), ftf(v.y), ftf(v.z), ftf(v.w));
        }
    }
    // out accumulators [mt 0..1][nt 0..3], bias preloaded
    float o[2][4][4];
    #pragma unroll
    for (int nt = 0; nt < 4; nt++) {
        float b0 = bout[wn * 32 + nt * 8 + 2 * t4];
        float b1 = bout[wn * 32 + nt * 8 + 2 * t4 + 1];
        #pragma unroll
        for (int mt = 0; mt < 2; mt++) {
            o[mt][nt][0] = b0; o[mt][nt][1] = b1;
            o[mt][nt][2] = b0; o[mt][nt][3] = b1;
        }
    }

    for (int h = 0; h < HEADS; h++) {
        // ===== B1: QKV. warp (wm,wn): rows wm*32+mt*16, qkv cols wn*8 =====
        float d1[3][2][4] = {};
        #pragma unroll 1
        for (int c = 0; c < 16; c++) {
            if (c == 15) cp_wait<0>(); else cp_wait<1>();
            __syncthreads();
            if (c < 14) issueW(h, c + 2, (c + 2) % 3);
            const float* wb = sm + WS_OFF + (c % 3) * WSLOT;
            const int kc = c * 16;
            #pragma unroll
            for (int ks = 0; ks < 2; ks++) {
                uint32_t a[2][4];
                ldsm4(a[0], xs_lds + ((kc + ks * 8) << 2));
                ldsm4(a[1], xs_lds + ((16 * XS_STR + kc + ks * 8) << 2));
                const float* wr = wb + ks * 8 * WS_STR + (wn << 3) + g4;
                #pragma unroll
                for (int m = 0; m < 3; m++) {
                    const float* wc = wr + m * 64;
                    uint32_t b[2] = { ftfu(wc[t4 * WS_STR]), ftfu(wc[(t4 + 4) * WS_STR]) };
                    mma8(d1[m][0], a[0], b);
                    mma8(d1[m][1], a[1], b);
                }
            }
        }
        // write Q/K/V (tf32)
        {
            const int cc = wn * 8 + 2 * t4;
            #pragma unroll
            for (int m = 0; m < 3; m++) {
                float* dst = sm + (m == 0 ? QS_OFF : m == 1 ? KS_OFF : VS_OFF);
                const int str = (m == 2) ? VS_STR : QS_STR;
                #pragma unroll
                for (int mt = 0; mt < 2; mt++) {
                    int r0 = wm * 32 + mt * 16 + g4;
                    dst[r0 * str + cc]           = ftf(d1[m][mt][0]);
                    dst[r0 * str + cc + 1]       = ftf(d1[m][mt][1]);
                    dst[(r0 + 8) * str + cc]     = ftf(d1[m][mt][2]);
                    dst[(r0 + 8) * str + cc + 1] = ftf(d1[m][mt][3]);
                }
            }
        }
        __syncthreads();

        // ===== B2a: S = Q K^T. 16 tiles: grp(w>>3) x mtq((w>>2)&1) x nt(w&3) =====
        {
            const int grp = w >> 3, mtq = (w >> 2) & 1, nt = w & 3;
            float s[4] = {};
            #pragma unroll
            for (int ks = 0; ks < 8; ks++) {
                uint32_t a[4];
                ldsm4(a, qs_lds + ((ks * 8) << 2));
                const float* kb = sm + KS_OFF + (grp * 32 + nt * 8 + g4) * KS_STR + ks * 8;
                uint32_t b[2] = { __float_as_uint(kb[t4]), __float_as_uint(kb[t4 + 4]) };
                mma8(s, a, b);
            }
            const int r0 = grp * 32 + mtq * 16 + g4, cc = nt * 8 + 2 * t4;
            sm[PS_OFF + r0 * PS_STR + cc]           = s[0] * 0.125f;
            sm[PS_OFF + r0 * PS_STR + cc + 1]       = s[1] * 0.125f;
            sm[PS_OFF + (r0 + 8) * PS_STR + cc]     = s[2] * 0.125f;
            sm[PS_OFF + (r0 + 8) * PS_STR + cc + 1] = s[3] * 0.125f;
        }
        __syncthreads();

        // ===== B2b: softmax, 64 rows, 8 threads/row (4 cols each) =====
        {
            const int i = tid >> 3, cb = tid & 7;
            float sv[4];
            #pragma unroll
            for (int jj = 0; jj < 4; jj++) sv[jj] = sm[PS_OFF + i * PS_STR + cb + jj * 8];
            float mx = fmaxf(fmaxf(sv[0], sv[1]), fmaxf(sv[2], sv[3]));
            #pragma unroll
            for (int msk = 1; msk < 8; msk <<= 1)
                mx = fmaxf(mx, __shfl_xor_sync(0xffffffffu, mx, msk));
            float sum = 0.f;
            #pragma unroll
            for (int jj = 0; jj < 4; jj++) { sv[jj] = __expf(sv[jj] - mx); sum += sv[jj]; }
            #pragma unroll
            for (int msk = 1; msk < 8; msk <<= 1)
                sum += __shfl_xor_sync(0xffffffffu, sum, msk);
            const float inv = 1.f / sum;
            #pragma unroll
            for (int jj = 0; jj < 4; jj++)
                sm[PS_OFF + i * PS_STR + cb + jj * 8] = ftf(sv[jj] * inv);
        }
        __syncthreads();
        issueWO(h, 0, 0); issueWO(h, 1, 1);   // prefetch Wout during B2c

        // ===== B2c: A = P V. warp: grp = w>>3, d-col group wn =====
        {
            const int grp = w >> 3;
            float dpv[2][4] = {};
            #pragma unroll
            for (int ks = 0; ks < 4; ks++) {
                const float* vb = sm + VS_OFF + (grp * 32 + ks * 8) * VS_STR + (wn << 3) + g4;
                uint32_t b[2] = { __float_as_uint(vb[t4 * VS_STR]),
                                  __float_as_uint(vb[(t4 + 4) * VS_STR]) };
                uint32_t a0[4], a1[4];
                ldsm4(a0, ps_lds + ((ks * 8) << 2));
                ldsm4(a1, ps_lds + ((16 * PS_STR + ks * 8) << 2));
                mma8(dpv[0], a0, b);
                mma8(dpv[1], a1, b);
            }
            const int cc = wn * 8 + 2 * t4;
            #pragma unroll
            for (int half = 0; half < 2; half++) {
                int r0 = grp * 32 + half * 16 + g4;
                sm[AS_OFF + r0 * AS_STR + cc]           = ftf(dpv[half][0]);
                sm[AS_OFF + r0 * AS_STR + cc + 1]       = ftf(dpv[half][1]);
                sm[AS_OFF + (r0 + 8) * AS_STR + cc]     = ftf(dpv[half][2]);
                sm[AS_OFF + (r0 + 8) * AS_STR + cc + 1] = ftf(dpv[half][3]);
            }
        }

        // ===== B3: out += A_h @ Wout. warp (wm,wn): rows wm*32.., n [wn*32,+32) =====
        #pragma unroll 1
        for (int c = 0; c < 8; c++) {
            if (c == 7) cp_wait<0>(); else cp_wait<1>();
            __syncthreads();
            if (c < 6) issueWO(h, c + 2, (c + 2) % 3);
            const int dc = c * 8;
            uint32_t a[2][4];
            ldsm4(a[0], as_lds + (dc << 2));
            ldsm4(a[1], as_lds + ((16 * AS_STR + dc) << 2));
            const float* wo = sm + WS_OFF + (c % 3) * WSLOT + (wn << 5) + g4;
            #pragma unroll
            for (int nt = 0; nt < 4; nt++) {
                const float* wc = wo + nt * 8;
                uint32_t b[2] = { ftfu(wc[t4 * WO_STR]), ftfu(wc[(t4 + 4) * WO_STR]) };
                mma8(o[0][nt], a[0], b);
                mma8(o[1][nt], a[1], b);
            }
        }
        __syncthreads();
        if (h < 7) { issueW(h + 1, 0, 0); issueW(h + 1, 1, 1); }
    }

    // ---- store ----
    #pragma unroll
    for (int mt = 0; mt < 2; mt++)
        #pragma unroll
        for (int nt = 0; nt < 4; nt++) {
            const int r0 = wm * 32 + mt * 16 + g4, cc = wn * 32 + nt * 8 + 2 * t4;
            float* p0 = out + ((size_t)blk * MR + r0) * DMODEL + cc;
            float* p1 = out + ((size_t)blk * MR + r0 + 8) * DMODEL + cc;
            *reinterpret_cast<float2*>(p0) = make_float2(o[mt][nt][0], o[mt][nt][1]);
            *reinterpret_cast<float2*>(p1) = make_float2(o[mt][nt][2], o[mt][nt][3]);
        }
}

extern "C" void kernel_launch(void* const* d_in, const int* in_sizes, int n_in,
                              void* d_out, int out_size)
{
    const float* x    = (const float*)d_in[0];   // [4,1024,32,256]
    const float* Wqkv = (const float*)d_in[1];   // [256,1536]
    const float* Wout = (const float*)d_in[2];   // [512,256]
    const float* bout = (const float*)d_in[3];   // [256]
    float* out = (float*)d_out;                  // [131072,256]

    cudaFuncSetAttribute(fused_attn_kernel,
                         cudaFuncAttributeMaxDynamicSharedMemorySize, SM_BYTES);
    fused_attn_kernel<<<GROUPS / NG, NT_THREADS, SM_BYTES>>>(x, Wqkv, Wout, bout, out);
}

// round 10
// speedup vs baseline: 2.2225x; 2.2225x over previous
#include <cuda_runtime.h>
#include <cuda_fp16.h>
#include <cstdint>

constexpr int TOK = 32, DMODEL = 256, HEADS = 8, INNER = 512;
constexpr int NQKV = 1536, DHEAD = 64, MR = 64;
constexpr int GRID = 2048;            // 131072 rows / 64

// fp16 copies of inputs (built by prep kernels each call)
__device__ __half g_xh[33554432];     // x   [131072][256]
__device__ __half g_wq[393216];       // Wqkv[256][1536]
__device__ __half g_wo[131072];       // Wout[512][256]

// ---- smem plan (HALF offsets). All LDSM arrays: row stride ≡ 8 (mod 64) ----
constexpr int XS_OFF = 0,      XS_STR = 264;        // x   [64][256]
constexpr int RG_OFF = 16896,  RSLOT = 6400;        // W ring: 2 slots
constexpr int WS_STR = 200;                         //   B1 chunk [32k][192]
constexpr int WO_STR = 264;                         //   B3 chunk [16k][256]
constexpr int QS_OFF = 29696;                       // Q [64][64] str 72
constexpr int KS_OFF = 34304, VS_OFF = 38912;
constexpr int AS_OFF = 43520, PH_OFF = 48128;       // A, P(fp16) [64][64/32] str 72
constexpr int S64 = 72;
constexpr int PSF_H = 52736;                        // S fp32 [64][33] (float view)
constexpr int SM_BYTES = 113920;                    // 2 blocks/SM

__device__ __forceinline__ void mmah(float* d, const uint32_t* a, const uint32_t* b) {
    asm volatile("mma.sync.aligned.m16n8k16.row.col.f32.f16.f16.f32 "
                 "{%0,%1,%2,%3},{%4,%5,%6,%7},{%8,%9},{%0,%1,%2,%3};"
                 : "+f"(d[0]), "+f"(d[1]), "+f"(d[2]), "+f"(d[3])
                 : "r"(a[0]), "r"(a[1]), "r"(a[2]), "r"(a[3]), "r"(b[0]), "r"(b[1]));
}
__device__ __forceinline__ void ldsm4(uint32_t* r, uint32_t sa) {
    asm volatile("ldmatrix.sync.aligned.m8n8.x4.shared.b16 {%0,%1,%2,%3}, [%4];"
                 : "=r"(r[0]), "=r"(r[1]), "=r"(r[2]), "=r"(r[3]) : "r"(sa));
}
__device__ __forceinline__ void ldsm4t(uint32_t* r, uint32_t sa) {
    asm volatile("ldmatrix.sync.aligned.m8n8.x4.trans.shared.b16 {%0,%1,%2,%3}, [%4];"
                 : "=r"(r[0]), "=r"(r[1]), "=r"(r[2]), "=r"(r[3]) : "r"(sa));
}
__device__ __forceinline__ void cpa16(uint32_t dst, const void* src) {
    asm volatile("cp.async.ca.shared.global [%0], [%1], 16;" :: "r"(dst), "l"(src));
}
__device__ __forceinline__ void cp_commit() { asm volatile("cp.async.commit_group;"); }
template<int N> __device__ __forceinline__ void cp_wait() {
    asm volatile("cp.async.wait_group %0;" :: "n"(N));
}
__device__ __forceinline__ void st_h2(__half* p, float lo, float hi) {
    *reinterpret_cast<__half2*>(p) = __floats2half2_rn(lo, hi);
}

// ---- prep: fp32 -> fp16 ----
__global__ void cvt_x_kernel(const float* __restrict__ src) {
    int i = blockIdx.x * 256 + threadIdx.x;            // 8388608 float4s
    float4 v = reinterpret_cast<const float4*>(src)[i];
    reinterpret_cast<__half2*>(g_xh)[2*i]   = __floats2half2_rn(v.x, v.y);
    reinterpret_cast<__half2*>(g_xh)[2*i+1] = __floats2half2_rn(v.z, v.w);
}
__global__ void cvt_w_kernel(const float* __restrict__ wq, const float* __restrict__ wo) {
    int i = blockIdx.x * 256 + threadIdx.x;            // 98304 + 32768 float4s
    if (i < 98304) {
        float4 v = reinterpret_cast<const float4*>(wq)[i];
        reinterpret_cast<__half2*>(g_wq)[2*i]   = __floats2half2_rn(v.x, v.y);
        reinterpret_cast<__half2*>(g_wq)[2*i+1] = __floats2half2_rn(v.z, v.w);
    } else {
        int j = i - 98304;
        float4 v = reinterpret_cast<const float4*>(wo)[j];
        reinterpret_cast<__half2*>(g_wo)[2*j]   = __floats2half2_rn(v.x, v.y);
        reinterpret_cast<__half2*>(g_wo)[2*j+1] = __floats2half2_rn(v.z, v.w);
    }
}

__global__ __launch_bounds__(256, 2)
void fused_attn_kernel(const float* __restrict__ bout, float* __restrict__ out)
{
    extern __shared__ __half smh[];
    const int tid = threadIdx.x;
    const int blk = blockIdx.x;          // rows blk*64 .. +63
    const int w   = tid >> 5;
    const int ln  = tid & 31;
    const int g4  = ln >> 2, t4 = ln & 3;
    const int wm  = w >> 2, wn = w & 3;  // B1/B3 tile coords
    const int arow = ln & 15, acol8 = (ln >> 4) * 8;         // A & trans-B lanes
    const int brow = ((ln >> 4) << 3) + (ln & 7);            // plain-B lanes
    const int bcol8 = ((ln >> 3) & 1) * 8;

    const uint32_t sb = (uint32_t)__cvta_generic_to_shared(smh);
    auto shalf = [&](int idx) { return sb + ((uint32_t)idx << 1); };

    // staging index precompute
    int wdst[3], wsrc[3];
    #pragma unroll
    for (int it = 0; it < 3; it++) {     // B1 chunk: 768 granules
        int l = tid + it * 256, kk = l / 24, gc = (l % 24) * 8;
        wdst[it] = kk * WS_STR + gc;
        wsrc[it] = kk * NQKV + (gc >> 6) * INNER + (gc & 63);
    }
    int odst[2], osrc[2];
    #pragma unroll
    for (int it = 0; it < 2; it++) {     // B3 chunk: 512 granules
        int l = tid + it * 256, dd = l >> 5, gc = (l & 31) * 8;
        odst[it] = dd * WO_STR + gc;
        osrc[it] = dd * 256 + gc;
    }
    auto issueW = [&](int h, int c, int p) {
        const __half* src = g_wq + c * 32 * NQKV + h * DHEAD;
        #pragma unroll
        for (int it = 0; it < 3; it++)
            cpa16(shalf(RG_OFF + p * RSLOT + wdst[it]), src + wsrc[it]);
        cp_commit();
    };
    auto issueWO = [&](int h, int c, int p) {
        const __half* src = g_wo + (h * DHEAD + c * 16) * 256;
        #pragma unroll
        for (int it = 0; it < 2; it++)
            cpa16(shalf(RG_OFF + p * RSLOT + odst[it]), src + osrc[it]);
        cp_commit();
    };

    issueW(0, 0, 0);
    {   // stage x[64][256] fp16
        const __half* xs = g_xh + (size_t)blk * (MR * DMODEL);
        #pragma unroll
        for (int it = 0; it < 8; it++) {
            int l = tid + it * 256, row = l >> 5, gc = (l & 31) * 8;
            cpa16(shalf(XS_OFF + row * XS_STR + gc), xs + row * 256 + gc);
        }
        cp_commit();
    }
    // out accumulators [mt 0..1][nt 0..7], bias preloaded
    float o[2][8][4];
    #pragma unroll
    for (int nt = 0; nt < 8; nt++) {
        float b0 = bout[wn * 64 + nt * 8 + 2 * t4];
        float b1 = bout[wn * 64 + nt * 8 + 2 * t4 + 1];
        #pragma unroll
        for (int mt = 0; mt < 2; mt++) {
            o[mt][nt][0] = b0; o[mt][nt][1] = b1;
            o[mt][nt][2] = b0; o[mt][nt][3] = b1;
        }
    }

    for (int h = 0; h < HEADS; h++) {
        // ===== B1: QKV. warp (wm,wn): rows wm*32.., qkv cols [wn*48,+48) =====
        float d1[2][6][4] = {};
        #pragma unroll 1
        for (int c = 0; c < 8; c++) {
            if (c < 7) issueW(h, c + 1, (c + 1) & 1);
            else       issueWO(h, 0, 0);
            cp_wait<1>(); __syncthreads();
            const int wbase = RG_OFF + (c & 1) * RSLOT;
            #pragma unroll
            for (int ks = 0; ks < 2; ks++) {
                uint32_t a[2][4];
                ldsm4(a[0], shalf(XS_OFF + (wm*32      + arow) * XS_STR + c*32 + ks*16 + acol8));
                ldsm4(a[1], shalf(XS_OFF + (wm*32 + 16 + arow) * XS_STR + c*32 + ks*16 + acol8));
                #pragma unroll
                for (int p = 0; p < 3; p++) {
                    uint32_t b[4];
                    ldsm4t(b, shalf(wbase + (ks*16 + arow) * WS_STR + wn*48 + p*16 + acol8));
                    mmah(d1[0][2*p],   a[0], b);
                    mmah(d1[0][2*p+1], a[0], b + 2);
                    mmah(d1[1][2*p],   a[1], b);
                    mmah(d1[1][2*p+1], a[1], b + 2);
                }
            }
            __syncthreads();
        }
        // write Q/K/V fp16
        #pragma unroll
        for (int nt = 0; nt < 6; nt++) {
            const int gcol = wn * 48 + nt * 8 + 2 * t4;
            const int sec = gcol >> 6, dcol = gcol & 63;
            __half* dst = smh + (sec == 0 ? QS_OFF : sec == 1 ? KS_OFF : VS_OFF);
            #pragma unroll
            for (int mt = 0; mt < 2; mt++) {
                int r = wm * 32 + mt * 16 + g4;
                st_h2(dst + r * S64 + dcol,       d1[mt][nt][0], d1[mt][nt][1]);
                st_h2(dst + (r + 8) * S64 + dcol, d1[mt][nt][2], d1[mt][nt][3]);
            }
        }
        __syncthreads();

        // ===== B2a: S = Q K^T * 0.125 (fp32 out) =====
        {
            const int grp = w >> 2, mtq = (w >> 1) & 1, np = w & 1;
            float s[2][4] = {};
            #pragma unroll
            for (int kk = 0; kk < 4; kk++) {
                uint32_t a[4], b[4];
                ldsm4(a, shalf(QS_OFF + (grp*32 + mtq*16 + arow) * S64 + kk*16 + acol8));
                ldsm4(b, shalf(KS_OFF + (grp*32 + np*16 + brow) * S64 + kk*16 + bcol8));
                mmah(s[0], a, b);
                mmah(s[1], a, b + 2);
            }
            float* psf = reinterpret_cast<float*>(smh + PSF_H);
            const int r = grp * 32 + mtq * 16 + g4;
            #pragma unroll
            for (int ntl = 0; ntl < 2; ntl++) {
                const int cc = np * 16 + ntl * 8 + 2 * t4;
                psf[r * 33 + cc]           = s[ntl][0] * 0.125f;
                psf[r * 33 + cc + 1]       = s[ntl][1] * 0.125f;
                psf[(r + 8) * 33 + cc]     = s[ntl][2] * 0.125f;
                psf[(r + 8) * 33 + cc + 1] = s[ntl][3] * 0.125f;
            }
        }
        __syncthreads();

        // ===== B2b: softmax (fp32 in, fp16 out). 4 thr/row, 8 cols each =====
        {
            const int i = tid >> 2, cb = tid & 3;
            const float* pr = reinterpret_cast<const float*>(smh + PSF_H) + i * 33 + cb * 8;
            float sv[8];
            #pragma unroll
            for (int jj = 0; jj < 8; jj++) sv[jj] = pr[jj];
            float mx = sv[0];
            #pragma unroll
            for (int jj = 1; jj < 8; jj++) mx = fmaxf(mx, sv[jj]);
            mx = fmaxf(mx, __shfl_xor_sync(0xffffffffu, mx, 1));
            mx = fmaxf(mx, __shfl_xor_sync(0xffffffffu, mx, 2));
            float sum = 0.f;
            #pragma unroll
            for (int jj = 0; jj < 8; jj++) { sv[jj] = __expf(sv[jj] - mx); sum += sv[jj]; }
            sum += __shfl_xor_sync(0xffffffffu, sum, 1);
            sum += __shfl_xor_sync(0xffffffffu, sum, 2);
            const float inv = 1.f / sum;
            __half* ph = smh + PH_OFF + i * S64 + cb * 8;
            #pragma unroll
            for (int jj = 0; jj < 4; jj++)
                st_h2(ph + 2 * jj, sv[2*jj] * inv, sv[2*jj+1] * inv);
        }
        __syncthreads();
        issueWO(h, 1, 1);

        // ===== B2c: A = P V. warp (grp = w>>2, d-block dq = w&3) =====
        {
            const int grp = w >> 2, dq = w & 3;
            float pv[2][2][4] = {};
            #pragma unroll
            for (int kk = 0; kk < 2; kk++) {
                uint32_t a0[4], a1[4], b[4];
                ldsm4(a0, shalf(PH_OFF + (grp*32      + arow) * S64 + kk*16 + acol8));
                ldsm4(a1, shalf(PH_OFF + (grp*32 + 16 + arow) * S64 + kk*16 + acol8));
                ldsm4t(b, shalf(VS_OFF + (grp*32 + kk*16 + arow) * S64 + dq*16 + acol8));
                mmah(pv[0][0], a0, b); mmah(pv[0][1], a0, b + 2);
                mmah(pv[1][0], a1, b); mmah(pv[1][1], a1, b + 2);
            }
            #pragma unroll
            for (int mt = 0; mt < 2; mt++)
                #pragma unroll
                for (int ntl = 0; ntl < 2; ntl++) {
                    const int r = grp * 32 + mt * 16 + g4;
                    const int cc = dq * 16 + ntl * 8 + 2 * t4;
                    st_h2(smh + AS_OFF + r * S64 + cc,       pv[mt][ntl][0], pv[mt][ntl][1]);
                    st_h2(smh + AS_OFF + (r + 8) * S64 + cc, pv[mt][ntl][2], pv[mt][ntl][3]);
                }
        }
        __syncthreads();

        // ===== B3: out += A_h @ Wout. warp (wm,wn): rows wm*32.., n [wn*64,+64) =====
        #pragma unroll 1
        for (int c = 0; c < 4; c++) {
            if (c == 1 || c == 2) issueWO(h, c + 1, (c + 1) & 1);
            else if (c == 3 && h < 7) issueW(h + 1, 0, 0);
            if (c == 3 && h == 7) cp_wait<0>(); else cp_wait<1>();
            __syncthreads();
            uint32_t a[2][4];
            ldsm4(a[0], shalf(AS_OFF + (wm*32      + arow) * S64 + c*16 + acol8));
            ldsm4(a[1], shalf(AS_OFF + (wm*32 + 16 + arow) * S64 + c*16 + acol8));
            const int wbase = RG_OFF + (c & 1) * RSLOT;
            #pragma unroll
            for (int np2 = 0; np2 < 4; np2++) {
                uint32_t b[4];
                ldsm4t(b, shalf(wbase + arow * WO_STR + wn*64 + np2*16 + acol8));
                mmah(o[0][2*np2],   a[0], b);
                mmah(o[0][2*np2+1], a[0], b + 2);
                mmah(o[1][2*np2],   a[1], b);
                mmah(o[1][2*np2+1], a[1], b + 2);
            }
            __syncthreads();
        }
    }

    // ---- store: rows blk*64 + wm*32 + mt*16 + g4 (+8), cols wn*64 + nt*8 + 2t4 ----
    #pragma unroll
    for (int mt = 0; mt < 2; mt++)
        #pragma unroll
        for (int nt = 0; nt < 8; nt++) {
            const int r0 = wm * 32 + mt * 16 + g4, cc = wn * 64 + nt * 8 + 2 * t4;
            float* p0 = out + ((size_t)blk * MR + r0) * DMODEL + cc;
            float* p1 = out + ((size_t)blk * MR + r0 + 8) * DMODEL + cc;
            *reinterpret_cast<float2*>(p0) = make_float2(o[mt][nt][0], o[mt][nt][1]);
            *reinterpret_cast<float2*>(p1) = make_float2(o[mt][nt][2], o[mt][nt][3]);
        }
}

extern "C" void kernel_launch(void* const* d_in, const int* in_sizes, int n_in,
                              void* d_out, int out_size)
{
    const float* x    = (const float*)d_in[0];   // [4,1024,32,256]
    const float* Wqkv = (const float*)d_in[1];   // [256,1536]
    const float* Wout = (const float*)d_in[2];   // [512,256]
    const float* bout = (const float*)d_in[3];   // [256]
    float* out = (float*)d_out;                  // [131072,256]

    cvt_x_kernel<<<32768, 256>>>(x);                    // 8388608 float4s
    cvt_w_kernel<<<512, 256>>>(Wqkv, Wout);             // 131072 float4s

    cudaFuncSetAttribute(fused_attn_kernel,
                         cudaFuncAttributeMaxDynamicSharedMemorySize, SM_BYTES);
    fused_attn_kernel<<<GRID, 256, SM_BYTES>>>(bout, out);
}

// round 11
// speedup vs baseline: 2.2583x; 1.0161x over previous
#include <cuda_runtime.h>
#include <cuda_fp16.h>
#include <cstdint>

constexpr int TOK = 32, DMODEL = 256, HEADS = 8, INNER = 512;
constexpr int NQKV = 1536, DHEAD = 64, MR = 64;
constexpr int GRID = 2048;            // 131072 rows / 64

// fp16 copies of weights (built by prep kernel each call)
__device__ __half g_wq[393216];       // Wqkv[256][1536]
__device__ __half g_wo[131072];       // Wout[512][256]

// ---- smem plan (HALF offsets). All LDSM arrays: row stride ≡ 8 (mod 64) ----
constexpr int XS_OFF = 0,      XS_STR = 264;        // x   [64][256]
constexpr int RG_OFF = 16896,  RSLOT = 6400;        // W ring: 2 slots
constexpr int WS_STR = 200;                         //   B1 chunk [32k][192]
constexpr int WO_STR = 264;                         //   B3 chunk [16k][256]
constexpr int QS_OFF = 29696;                       // Q [64][64] str 72
constexpr int KS_OFF = 34304, VS_OFF = 38912;
constexpr int AS_OFF = 43520, PH_OFF = 48128;       // A, P(fp16) [64][64/32] str 72
constexpr int S64 = 72;
constexpr int PSF_H = 52736;                        // S fp32 [64][33] (float view)
constexpr int SM_BYTES = 113920;                    // 2 blocks/SM

__device__ __forceinline__ void mmah(float* d, const uint32_t* a, const uint32_t* b) {
    asm volatile("mma.sync.aligned.m16n8k16.row.col.f32.f16.f16.f32 "
                 "{%0,%1,%2,%3},{%4,%5,%6,%7},{%8,%9},{%0,%1,%2,%3};"
                 : "+f"(d[0]), "+f"(d[1]), "+f"(d[2]), "+f"(d[3])
                 : "r"(a[0]), "r"(a[1]), "r"(a[2]), "r"(a[3]), "r"(b[0]), "r"(b[1]));
}
__device__ __forceinline__ void ldsm4(uint32_t* r, uint32_t sa) {
    asm volatile("ldmatrix.sync.aligned.m8n8.x4.shared.b16 {%0,%1,%2,%3}, [%4];"
                 : "=r"(r[0]), "=r"(r[1]), "=r"(r[2]), "=r"(r[3]) : "r"(sa));
}
__device__ __forceinline__ void ldsm4t(uint32_t* r, uint32_t sa) {
    asm volatile("ldmatrix.sync.aligned.m8n8.x4.trans.shared.b16 {%0,%1,%2,%3}, [%4];"
                 : "=r"(r[0]), "=r"(r[1]), "=r"(r[2]), "=r"(r[3]) : "r"(sa));
}
__device__ __forceinline__ void cpa16(uint32_t dst, const void* src) {
    asm volatile("cp.async.ca.shared.global [%0], [%1], 16;" :: "r"(dst), "l"(src));
}
__device__ __forceinline__ void cp_commit() { asm volatile("cp.async.commit_group;"); }
template<int N> __device__ __forceinline__ void cp_wait() {
    asm volatile("cp.async.wait_group %0;" :: "n"(N));
}
__device__ __forceinline__ void st_h2(__half* p, float lo, float hi) {
    *reinterpret_cast<__half2*>(p) = __floats2half2_rn(lo, hi);
}

// ---- prep: weights fp32 -> fp16 (tiny; x converts in-kernel) ----
__global__ void cvt_w_kernel(const float* __restrict__ wq, const float* __restrict__ wo) {
    int i = blockIdx.x * 256 + threadIdx.x;            // 98304 + 32768 float4s
    if (i < 98304) {
        float4 v = reinterpret_cast<const float4*>(wq)[i];
        reinterpret_cast<__half2*>(g_wq)[2*i]   = __floats2half2_rn(v.x, v.y);
        reinterpret_cast<__half2*>(g_wq)[2*i+1] = __floats2half2_rn(v.z, v.w);
    } else {
        int j = i - 98304;
        float4 v = reinterpret_cast<const float4*>(wo)[j];
        reinterpret_cast<__half2*>(g_wo)[2*j]   = __floats2half2_rn(v.x, v.y);
        reinterpret_cast<__half2*>(g_wo)[2*j+1] = __floats2half2_rn(v.z, v.w);
    }
}

__global__ __launch_bounds__(256, 2)
void fused_attn_kernel(const float* __restrict__ x,
                       const float* __restrict__ bout,
                       float* __restrict__ out)
{
    extern __shared__ __half smh[];
    const int tid = threadIdx.x;
    const int blk = blockIdx.x;          // rows blk*64 .. +63
    const int w   = tid >> 5;
    const int ln  = tid & 31;
    const int g4  = ln >> 2, t4 = ln & 3;
    const int wm  = w >> 2, wn = w & 3;  // B1/B3 tile coords
    const int arow = ln & 15, acol8 = (ln >> 4) * 8;         // A & trans-B lanes
    const int brow = ((ln >> 4) << 3) + (ln & 7);            // plain-B lanes
    const int bcol8 = ((ln >> 3) & 1) * 8;

    const uint32_t sb = (uint32_t)__cvta_generic_to_shared(smh);
    auto shalf = [&](int idx) { return sb + ((uint32_t)idx << 1); };

    // staging index precompute
    int wdst[3], wsrc[3];
    #pragma unroll
    for (int it = 0; it < 3; it++) {     // B1 chunk: 768 granules
        int l = tid + it * 256, kk = l / 24, gc = (l % 24) * 8;
        wdst[it] = kk * WS_STR + gc;
        wsrc[it] = kk * NQKV + (gc >> 6) * INNER + (gc & 63);
    }
    int odst[2], osrc[2];
    #pragma unroll
    for (int it = 0; it < 2; it++) {     // B3 chunk: 512 granules
        int l = tid + it * 256, dd = l >> 5, gc = (l & 31) * 8;
        odst[it] = dd * WO_STR + gc;
        osrc[it] = dd * 256 + gc;
    }
    auto issueW = [&](int h, int c, int p) {
        const __half* src = g_wq + c * 32 * NQKV + h * DHEAD;
        #pragma unroll
        for (int it = 0; it < 3; it++)
            cpa16(shalf(RG_OFF + p * RSLOT + wdst[it]), src + wsrc[it]);
        cp_commit();
    };
    auto issueWO = [&](int h, int c, int p) {
        const __half* src = g_wo + (h * DHEAD + c * 16) * 256;
        #pragma unroll
        for (int it = 0; it < 2; it++)
            cpa16(shalf(RG_OFF + p * RSLOT + odst[it]), src + osrc[it]);
        cp_commit();
    };

    issueW(0, 0, 0);

    // stage x[64][256]: fp32 LDG -> fp16 STS (overlaps W chunk0 fetch)
    {
        const float4* xg = reinterpret_cast<const float4*>(x + (size_t)blk * MR * DMODEL);
        #pragma unroll
        for (int it = 0; it < 16; it++) {
            int l = tid + it * 256;          // 4096 float4s
            int row = l >> 6, c4 = l & 63;
            float4 v = xg[l];
            __half* d = smh + XS_OFF + row * XS_STR + c4 * 4;
            *reinterpret_cast<__half2*>(d)     = __floats2half2_rn(v.x, v.y);
            *reinterpret_cast<__half2*>(d + 2) = __floats2half2_rn(v.z, v.w);
        }
    }
    // out accumulators [mt 0..1][nt 0..7], bias preloaded
    float o[2][8][4];
    #pragma unroll
    for (int nt = 0; nt < 8; nt++) {
        float b0 = bout[wn * 64 + nt * 8 + 2 * t4];
        float b1 = bout[wn * 64 + nt * 8 + 2 * t4 + 1];
        #pragma unroll
        for (int mt = 0; mt < 2; mt++) {
            o[mt][nt][0] = b0; o[mt][nt][1] = b1;
            o[mt][nt][2] = b0; o[mt][nt][3] = b1;
        }
    }

    for (int h = 0; h < HEADS; h++) {
        // ===== B1: QKV. warp (wm,wn): rows wm*32.., qkv cols [wn*48,+48) =====
        // Single-sync pipeline: wait(all) -> sync -> issue(c+1) -> compute(c).
        float d1[2][6][4] = {};
        #pragma unroll 1
        for (int c = 0; c < 8; c++) {
            cp_wait<0>(); __syncthreads();
            if (c < 7) issueW(h, c + 1, (c + 1) & 1);
            else       issueWO(h, 0, 0);
            const int wbase = RG_OFF + (c & 1) * RSLOT;
            #pragma unroll
            for (int ks = 0; ks < 2; ks++) {
                uint32_t a[2][4];
                ldsm4(a[0], shalf(XS_OFF + (wm*32      + arow) * XS_STR + c*32 + ks*16 + acol8));
                ldsm4(a[1], shalf(XS_OFF + (wm*32 + 16 + arow) * XS_STR + c*32 + ks*16 + acol8));
                #pragma unroll
                for (int p = 0; p < 3; p++) {
                    uint32_t b[4];
                    ldsm4t(b, shalf(wbase + (ks*16 + arow) * WS_STR + wn*48 + p*16 + acol8));
                    mmah(d1[0][2*p],   a[0], b);
                    mmah(d1[0][2*p+1], a[0], b + 2);
                    mmah(d1[1][2*p],   a[1], b);
                    mmah(d1[1][2*p+1], a[1], b + 2);
                }
            }
        }
        // write Q/K/V fp16 (warp-disjoint regions; sync below orders vs B2a)
        #pragma unroll
        for (int nt = 0; nt < 6; nt++) {
            const int gcol = wn * 48 + nt * 8 + 2 * t4;
            const int sec = gcol >> 6, dcol = gcol & 63;
            __half* dst = smh + (sec == 0 ? QS_OFF : sec == 1 ? KS_OFF : VS_OFF);
            #pragma unroll
            for (int mt = 0; mt < 2; mt++) {
                int r = wm * 32 + mt * 16 + g4;
                st_h2(dst + r * S64 + dcol,       d1[mt][nt][0], d1[mt][nt][1]);
                st_h2(dst + (r + 8) * S64 + dcol, d1[mt][nt][2], d1[mt][nt][3]);
            }
        }
        __syncthreads();

        // ===== B2a: S = Q K^T * 0.125 (fp32 out) =====
        {
            const int grp = w >> 2, mtq = (w >> 1) & 1, np = w & 1;
            float s[2][4] = {};
            #pragma unroll
            for (int kk = 0; kk < 4; kk++) {
                uint32_t a[4], b[4];
                ldsm4(a, shalf(QS_OFF + (grp*32 + mtq*16 + arow) * S64 + kk*16 + acol8));
                ldsm4(b, shalf(KS_OFF + (grp*32 + np*16 + brow) * S64 + kk*16 + bcol8));
                mmah(s[0], a, b);
                mmah(s[1], a, b + 2);
            }
            float* psf = reinterpret_cast<float*>(smh + PSF_H);
            const int r = grp * 32 + mtq * 16 + g4;
            #pragma unroll
            for (int ntl = 0; ntl < 2; ntl++) {
                const int cc = np * 16 + ntl * 8 + 2 * t4;
                psf[r * 33 + cc]           = s[ntl][0] * 0.125f;
                psf[r * 33 + cc + 1]       = s[ntl][1] * 0.125f;
                psf[(r + 8) * 33 + cc]     = s[ntl][2] * 0.125f;
                psf[(r + 8) * 33 + cc + 1] = s[ntl][3] * 0.125f;
            }
        }
        __syncthreads();

        // ===== B2b: softmax (fp32 in, fp16 out). 4 thr/row, 8 cols each =====
        {
            const int i = tid >> 2, cb = tid & 3;
            const float* pr = reinterpret_cast<const float*>(smh + PSF_H) + i * 33 + cb * 8;
            float sv[8];
            #pragma unroll
            for (int jj = 0; jj < 8; jj++) sv[jj] = pr[jj];
            float mx = sv[0];
            #pragma unroll
            for (int jj = 1; jj < 8; jj++) mx = fmaxf(mx, sv[jj]);
            mx = fmaxf(mx, __shfl_xor_sync(0xffffffffu, mx, 1));
            mx = fmaxf(mx, __shfl_xor_sync(0xffffffffu, mx, 2));
            float sum = 0.f;
            #pragma unroll
            for (int jj = 0; jj < 8; jj++) { sv[jj] = __expf(sv[jj] - mx); sum += sv[jj]; }
            sum += __shfl_xor_sync(0xffffffffu, sum, 1);
            sum += __shfl_xor_sync(0xffffffffu, sum, 2);
            const float inv = 1.f / sum;
            __half* ph = smh + PH_OFF + i * S64 + cb * 8;
            #pragma unroll
            for (int jj = 0; jj < 4; jj++)
                st_h2(ph + 2 * jj, sv[2*jj] * inv, sv[2*jj+1] * inv);
        }
        __syncthreads();

        // ===== B2c: A = P V. warp (grp = w>>2, d-block dq = w&3) =====
        {
            const int grp = w >> 2, dq = w & 3;
            float pv[2][2][4] = {};
            #pragma unroll
            for (int kk = 0; kk < 2; kk++) {
                uint32_t a0[4], a1[4], b[4];
                ldsm4(a0, shalf(PH_OFF + (grp*32      + arow) * S64 + kk*16 + acol8));
                ldsm4(a1, shalf(PH_OFF + (grp*32 + 16 + arow) * S64 + kk*16 + acol8));
                ldsm4t(b, shalf(VS_OFF + (grp*32 + kk*16 + arow) * S64 + dq*16 + acol8));
                mmah(pv[0][0], a0, b); mmah(pv[0][1], a0, b + 2);
                mmah(pv[1][0], a1, b); mmah(pv[1][1], a1, b + 2);
            }
            #pragma unroll
            for (int mt = 0; mt < 2; mt++)
                #pragma unroll
                for (int ntl = 0; ntl < 2; ntl++) {
                    const int r = grp * 32 + mt * 16 + g4;
                    const int cc = dq * 16 + ntl * 8 + 2 * t4;
                    st_h2(smh + AS_OFF + r * S64 + cc,       pv[mt][ntl][0], pv[mt][ntl][1]);
                    st_h2(smh + AS_OFF + (r + 8) * S64 + cc, pv[mt][ntl][2], pv[mt][ntl][3]);
                }
        }
        // (no sync here: B3 c=0's barrier orders AS writes before AS reads)

        // ===== B3: out += A_h @ Wout. warp (wm,wn): rows wm*32.., n [wn*64,+64) =====
        #pragma unroll 1
        for (int c = 0; c < 4; c++) {
            cp_wait<0>(); __syncthreads();
            if (c < 3)      issueWO(h, c + 1, (c + 1) & 1);
            else if (h < 7) issueW(h + 1, 0, 0);
            uint32_t a[2][4];
            ldsm4(a[0], shalf(AS_OFF + (wm*32      + arow) * S64 + c*16 + acol8));
            ldsm4(a[1], shalf(AS_OFF + (wm*32 + 16 + arow) * S64 + c*16 + acol8));
            const int wbase = RG_OFF + (c & 1) * RSLOT;
            #pragma unroll
            for (int np2 = 0; np2 < 4; np2++) {
                uint32_t b[4];
                ldsm4t(b, shalf(wbase + arow * WO_STR + wn*64 + np2*16 + acol8));
                mmah(o[0][2*np2],   a[0], b);
                mmah(o[0][2*np2+1], a[0], b + 2);
                mmah(o[1][2*np2],   a[1], b);
                mmah(o[1][2*np2+1], a[1], b + 2);
            }
        }
    }

    // ---- store: rows blk*64 + wm*32 + mt*16 + g4 (+8), cols wn*64 + nt*8 + 2t4 ----
    #pragma unroll
    for (int mt = 0; mt < 2; mt++)
        #pragma unroll
        for (int nt = 0; nt < 8; nt++) {
            const int r0 = wm * 32 + mt * 16 + g4, cc = wn * 64 + nt * 8 + 2 * t4;
            float* p0 = out + ((size_t)blk * MR + r0) * DMODEL + cc;
            float* p1 = out + ((size_t)blk * MR + r0 + 8) * DMODEL + cc;
            *reinterpret_cast<float2*>(p0) = make_float2(o[mt][nt][0], o[mt][nt][1]);
            *reinterpret_cast<float2*>(p1) = make_float2(o[mt][nt][2], o[mt][nt][3]);
        }
}

extern "C" void kernel_launch(void* const* d_in, const int* in_sizes, int n_in,
                              void* d_out, int out_size)
{
    const float* x    = (const float*)d_in[0];   // [4,1024,32,256]
    const float* Wqkv = (const float*)d_in[1];   // [256,1536]
    const float* Wout = (const float*)d_in[2];   // [512,256]
    const float* bout = (const float*)d_in[3];   // [256]
    float* out = (float*)d_out;                  // [131072,256]

    cvt_w_kernel<<<512, 256>>>(Wqkv, Wout);      // 131072 float4s

    cudaFuncSetAttribute(fused_attn_kernel,
                         cudaFuncAttributeMaxDynamicSharedMemorySize, SM_BYTES);
    fused_attn_kernel<<<GRID, 256, SM_BYTES>>>(x, bout, out);
}

// round 14
// speedup vs baseline: 2.3701x; 1.0495x over previous
#include <cuda_runtime.h>
#include <cuda_fp16.h>
#include <cstdint>

constexpr int DMODEL = 256, HEADS = 8, INNER = 512;
constexpr int NQKV = 1536, DHEAD = 64, MR = 64;
constexpr int GRID = 2048;            // 131072 rows / 64

// fp16 weights (prep kernel)
__device__ __half g_wq[393216];       // Wqkv[256][1536]
__device__ __half g_wo[131072];       // Wout[512][256]

// ---- smem plan (HALF offsets) ----
constexpr int XS_OFF = 0,     XS_STR = 264;       // x [64][256]
constexpr int RING_OFF = 16896;                   // 4 cg x 2 slots x 1792
constexpr int CG_STRIDE = 3584, SLOT = 1792;
constexpr int W1_STR = 56;                        // B1 slice [32k][48]
constexpr int W3_STR = 72;                        // B3 slice [16k][64] (aliases ring)
constexpr int S72 = 72;
constexpr int QS_OFF = 31232, KS_OFF = 35840, VS_OFF = 40448, AS_OFF = 45056;
constexpr int PH_OFF = 49664, PH_STR = 40;        // P fp16 [64][32]
constexpr int SM_BYTES = 104448;                  // 52224 halfs -> 2 blocks/SM

__device__ __forceinline__ void mmah(float* d, const uint32_t* a, const uint32_t* b) {
    asm volatile("mma.sync.aligned.m16n8k16.row.col.f32.f16.f16.f32 "
                 "{%0,%1,%2,%3},{%4,%5,%6,%7},{%8,%9},{%0,%1,%2,%3};"
                 : "+f"(d[0]), "+f"(d[1]), "+f"(d[2]), "+f"(d[3])
                 : "r"(a[0]), "r"(a[1]), "r"(a[2]), "r"(a[3]), "r"(b[0]), "r"(b[1]));
}
__device__ __forceinline__ void ldsm4(uint32_t* r, uint32_t sa) {
    asm volatile("ldmatrix.sync.aligned.m8n8.x4.shared.b16 {%0,%1,%2,%3}, [%4];"
                 : "=r"(r[0]), "=r"(r[1]), "=r"(r[2]), "=r"(r[3]) : "r"(sa));
}
__device__ __forceinline__ void ldsm4t(uint32_t* r, uint32_t sa) {
    asm volatile("ldmatrix.sync.aligned.m8n8.x4.trans.shared.b16 {%0,%1,%2,%3}, [%4];"
                 : "=r"(r[0]), "=r"(r[1]), "=r"(r[2]), "=r"(r[3]) : "r"(sa));
}
__device__ __forceinline__ void cpa16(uint32_t dst, const void* src) {
    asm volatile("cp.async.ca.shared.global [%0], [%1], 16;" :: "r"(dst), "l"(src));
}
__device__ __forceinline__ void cp_commit() { asm volatile("cp.async.commit_group;"); }
__device__ __forceinline__ void cp_wait0() {
    asm volatile("cp.async.wait_group 0;" ::: "memory");
}
__device__ __forceinline__ void st_h2(__half* p, float lo, float hi) {
    *reinterpret_cast<__half2*>(p) = __floats2half2_rn(lo, hi);
}
__device__ __forceinline__ uint32_t h2u(__half2 h) {
    return *reinterpret_cast<uint32_t*>(&h);
}

__global__ void cvt_w_kernel(const float* __restrict__ wq, const float* __restrict__ wo) {
    int i = blockIdx.x * 256 + threadIdx.x;
    if (i < 98304) {
        float4 v = reinterpret_cast<const float4*>(wq)[i];
        reinterpret_cast<__half2*>(g_wq)[2*i]   = __floats2half2_rn(v.x, v.y);
        reinterpret_cast<__half2*>(g_wq)[2*i+1] = __floats2half2_rn(v.z, v.w);
    } else {
        int j = i - 98304;
        float4 v = reinterpret_cast<const float4*>(wo)[j];
        reinterpret_cast<__half2*>(g_wo)[2*j]   = __floats2half2_rn(v.x, v.y);
        reinterpret_cast<__half2*>(g_wo)[2*j+1] = __floats2half2_rn(v.z, v.w);
    }
}

__global__ __launch_bounds__(256, 2)
void fused_attn_kernel(const float* __restrict__ x,
                       const float* __restrict__ bout,
                       float* __restrict__ out)
{
    extern __shared__ __half smh[];
    const int tid = threadIdx.x;
    const int blk = blockIdx.x;
    const int w   = tid >> 5, ln = tid & 31;
    const int g4  = ln >> 2, t4 = ln & 3;
    const int wm  = w >> 2, wn = w & 3;        // pair = {wn, wn+4}
    const bool lead = (wm == 0);
    const int arow = ln & 15, acol8 = (ln >> 4) * 8;
    const int brow = ((ln >> 4) << 3) + (ln & 7);
    const int bcol8 = ((ln >> 3) & 1) * 8;
    const int barid = wn + 1;

    const uint32_t sb = (uint32_t)__cvta_generic_to_shared(smh);
    auto shalf = [&](int idx) { return sb + ((uint32_t)idx << 1); };
    auto pbar = [&]() { asm volatile("bar.sync %0, 64;" :: "r"(barid) : "memory"); };

    const int ringcg = RING_OFF + wn * CG_STRIDE;

    // per-lane staging indices (leader warp lanes)
    int wkk[6], wj8[6], wsofs[6];   // B1 slice: 192 granules / 32 lanes
    #pragma unroll
    for (int it = 0; it < 6; it++) {
        int gi = it * 32 + ln, kk = gi / 6, j8 = (gi % 6) * 8;
        int gcol = wn * 48 + j8;
        wkk[it] = kk; wj8[it] = j8;
        wsofs[it] = kk * NQKV + (gcol >> 6) * INNER + (gcol & 63);
    }
    int odd_[4], oj8[4];     // B3 slice: 128 granules / 32 lanes
    #pragma unroll
    for (int it = 0; it < 4; it++) {
        int gi = it * 32 + ln;
        odd_[it] = gi >> 3; oj8[it] = (gi & 7) * 8;
    }
    auto issueW = [&](int h, int c, int p) {   // leader only
        const __half* src = g_wq + (size_t)c * 32 * NQKV + h * DHEAD;
        const uint32_t dst = shalf(ringcg + p * SLOT);
        #pragma unroll
        for (int it = 0; it < 6; it++)
            cpa16(dst + ((uint32_t)(wkk[it] * W1_STR + wj8[it]) << 1), src + wsofs[it]);
        cp_commit();
    };
    auto issueWO = [&](int h, int c, int p) {  // leader only
        const __half* src = g_wo + (size_t)(h * DHEAD + c * 16) * DMODEL + wn * 64;
        const uint32_t dst = shalf(ringcg + p * SLOT);
        #pragma unroll
        for (int it = 0; it < 4; it++)
            cpa16(dst + ((uint32_t)(odd_[it] * W3_STR + oj8[it]) << 1),
                  src + odd_[it] * DMODEL + oj8[it]);
        cp_commit();
    };

    if (lead) issueW(0, 0, 0);

    // stage x[64][256]: fp32 LDG -> fp16 STS.128 (8 halfs per granule)
    {
        const float4* xg = reinterpret_cast<const float4*>(x + (size_t)blk * MR * DMODEL);
        #pragma unroll
        for (int it = 0; it < 8; it++) {
            int gidx = tid + it * 256;            // 2048 granules
            int row = gidx >> 5, col8 = (gidx & 31) * 8;
            int base4 = (row * DMODEL + col8) >> 2;
            float4 v0 = xg[base4];
            float4 v1 = xg[base4 + 1];
            uint4 pk;
            pk.x = h2u(__floats2half2_rn(v0.x, v0.y));
            pk.y = h2u(__floats2half2_rn(v0.z, v0.w));
            pk.z = h2u(__floats2half2_rn(v1.x, v1.y));
            pk.w = h2u(__floats2half2_rn(v1.z, v1.w));
            *reinterpret_cast<uint4*>(smh + XS_OFF + row * XS_STR + col8) = pk;
        }
    }
    // out accumulators, bias preloaded
    float o[2][8][4];
    #pragma unroll
    for (int nt = 0; nt < 8; nt++) {
        float b0 = bout[wn * 64 + nt * 8 + 2 * t4];
        float b1 = bout[wn * 64 + nt * 8 + 2 * t4 + 1];
        #pragma unroll
        for (int mt = 0; mt < 2; mt++) {
            o[mt][nt][0] = b0; o[mt][nt][1] = b1;
            o[mt][nt][2] = b0; o[mt][nt][3] = b1;
        }
    }
    __syncthreads();   // XS visible to all

    for (int h = 0; h < HEADS; h++) {
        // ===== B1: QKV. pair-scoped ring; warp (wm,wn): rows wm*32.., cols wn*48 =====
        float d1[2][6][4] = {};
        #pragma unroll 1
        for (int c = 0; c < 8; c++) {
            if (lead) cp_wait0();
            pbar();
            if (lead) { if (c < 7) issueW(h, c + 1, (c + 1) & 1); else issueWO(h, 0, 0); }
            const int wb = ringcg + (c & 1) * SLOT;
            #pragma unroll
            for (int ks = 0; ks < 2; ks++) {
                uint32_t a[2][4];
                ldsm4(a[0], shalf(XS_OFF + (wm*32      + arow) * XS_STR + c*32 + ks*16 + acol8));
                ldsm4(a[1], shalf(XS_OFF + (wm*32 + 16 + arow) * XS_STR + c*32 + ks*16 + acol8));
                #pragma unroll
                for (int p = 0; p < 3; p++) {
                    uint32_t b[4];
                    ldsm4t(b, shalf(wb + (ks*16 + arow) * W1_STR + p*16 + acol8));
                    mmah(d1[0][2*p],   a[0], b);
                    mmah(d1[0][2*p+1], a[0], b + 2);
                    mmah(d1[1][2*p],   a[1], b);
                    mmah(d1[1][2*p+1], a[1], b + 2);
                }
            }
        }
        // write Q/K/V fp16
        #pragma unroll
        for (int nt = 0; nt < 6; nt++) {
            const int gcol = wn * 48 + nt * 8 + 2 * t4;
            const int sec = gcol >> 6, dcol = gcol & 63;
            __half* dst = smh + (sec == 0 ? QS_OFF : sec == 1 ? KS_OFF : VS_OFF);
            #pragma unroll
            for (int mt = 0; mt < 2; mt++) {
                int r = wm * 32 + mt * 16 + g4;
                st_h2(dst + r * S72 + dcol,       d1[mt][nt][0], d1[mt][nt][1]);
                st_h2(dst + (r + 8) * S72 + dcol, d1[mt][nt][2], d1[mt][nt][3]);
            }
        }
        __syncthreads();   // (1) QKV ready

        // ===== B2a + register softmax + P write. Warps 0-3: m-tile w, 32 cols =====
        if (w < 4) {
            const int mt = w, grp = w >> 1;
            float s[4][4] = {};
            #pragma unroll
            for (int kk = 0; kk < 4; kk++) {
                uint32_t a[4];
                ldsm4(a, shalf(QS_OFF + (mt*16 + arow) * S72 + kk*16 + acol8));
                #pragma unroll
                for (int np = 0; np < 2; np++) {
                    uint32_t b[4];
                    ldsm4(b, shalf(KS_OFF + (grp*32 + np*16 + brow) * S72 + kk*16 + bcol8));
                    mmah(s[np*2],   a, b);
                    mmah(s[np*2+1], a, b + 2);
                }
            }
            float mx0, mx1, sm0 = 0.f, sm1 = 0.f;
            #pragma unroll
            for (int nt = 0; nt < 4; nt++)
                #pragma unroll
                for (int q = 0; q < 4; q++) s[nt][q] *= 0.125f;
            mx0 = fmaxf(fmaxf(s[0][0], s[0][1]), fmaxf(s[1][0], s[1][1]));
            mx1 = fmaxf(fmaxf(s[0][2], s[0][3]), fmaxf(s[1][2], s[1][3]));
            mx0 = fmaxf(mx0, fmaxf(fmaxf(s[2][0], s[2][1]), fmaxf(s[3][0], s[3][1])));
            mx1 = fmaxf(mx1, fmaxf(fmaxf(s[2][2], s[2][3]), fmaxf(s[3][2], s[3][3])));
            #pragma unroll
            for (int msk = 1; msk < 4; msk <<= 1) {
                mx0 = fmaxf(mx0, __shfl_xor_sync(0xffffffffu, mx0, msk));
                mx1 = fmaxf(mx1, __shfl_xor_sync(0xffffffffu, mx1, msk));
            }
            #pragma unroll
            for (int nt = 0; nt < 4; nt++) {
                s[nt][0] = __expf(s[nt][0] - mx0); s[nt][1] = __expf(s[nt][1] - mx0);
                s[nt][2] = __expf(s[nt][2] - mx1); s[nt][3] = __expf(s[nt][3] - mx1);
                sm0 += s[nt][0] + s[nt][1];
                sm1 += s[nt][2] + s[nt][3];
            }
            #pragma unroll
            for (int msk = 1; msk < 4; msk <<= 1) {
                sm0 += __shfl_xor_sync(0xffffffffu, sm0, msk);
                sm1 += __shfl_xor_sync(0xffffffffu, sm1, msk);
            }
            const float i0 = 1.f / sm0, i1 = 1.f / sm1;
            const int r0 = mt * 16 + g4;
            #pragma unroll
            for (int nt = 0; nt < 4; nt++) {
                st_h2(smh + PH_OFF + r0 * PH_STR + nt*8 + 2*t4,       s[nt][0]*i0, s[nt][1]*i0);
                st_h2(smh + PH_OFF + (r0 + 8) * PH_STR + nt*8 + 2*t4, s[nt][2]*i1, s[nt][3]*i1);
            }
        }
        __syncthreads();   // (2) P ready

        // ===== B2c: A = P V. warp (grp = w>>2, d-block dq = w&3) =====
        {
            const int grp = w >> 2, dq = w & 3;
            float pv[2][2][4] = {};
            #pragma unroll
            for (int kk = 0; kk < 2; kk++) {
                uint32_t a0[4], a1[4], b[4];
                ldsm4(a0, shalf(PH_OFF + (grp*32      + arow) * PH_STR + kk*16 + acol8));
                ldsm4(a1, shalf(PH_OFF + (grp*32 + 16 + arow) * PH_STR + kk*16 + acol8));
                ldsm4t(b, shalf(VS_OFF + (grp*32 + kk*16 + arow) * S72 + dq*16 + acol8));
                mmah(pv[0][0], a0, b); mmah(pv[0][1], a0, b + 2);
                mmah(pv[1][0], a1, b); mmah(pv[1][1], a1, b + 2);
            }
            #pragma unroll
            for (int mt = 0; mt < 2; mt++)
                #pragma unroll
                for (int ntl = 0; ntl < 2; ntl++) {
                    const int r = grp * 32 + mt * 16 + g4;
                    const int cc = dq * 16 + ntl * 8 + 2 * t4;
                    st_h2(smh + AS_OFF + r * S72 + cc,       pv[mt][ntl][0], pv[mt][ntl][1]);
                    st_h2(smh + AS_OFF + (r + 8) * S72 + cc, pv[mt][ntl][2], pv[mt][ntl][3]);
                }
        }
        __syncthreads();   // (3) A ready

        // ===== B3: out += A_h @ Wout. pair ring (aliased); rows wm*32, n wn*64 =====
        #pragma unroll 1
        for (int c = 0; c < 4; c++) {
            if (lead) cp_wait0();
            pbar();
            if (lead) {
                if (c < 3)      issueWO(h, c + 1, (c + 1) & 1);
                else if (h < 7) issueW(h + 1, 0, 0);
            }
            const int wb = ringcg + (c & 1) * SLOT;
            uint32_t a[2][4];
            ldsm4(a[0], shalf(AS_OFF + (wm*32      + arow) * S72 + c*16 + acol8));
            ldsm4(a[1], shalf(AS_OFF + (wm*32 + 16 + arow) * S72 + c*16 + acol8));
            #pragma unroll
            for (int np2 = 0; np2 < 4; np2++) {
                uint32_t b[4];
                ldsm4t(b, shalf(wb + arow * W3_STR + np2*16 + acol8));
                mmah(o[0][2*np2],   a[0], b);
                mmah(o[0][2*np2+1], a[0], b + 2);
                mmah(o[1][2*np2],   a[1], b);
                mmah(o[1][2*np2+1], a[1], b + 2);
            }
        }
    }

    // ---- store ----
    #pragma unroll
    for (int mt = 0; mt < 2; mt++)
        #pragma unroll
        for (int nt = 0; nt < 8; nt++) {
            const int r0 = wm * 32 + mt * 16 + g4, cc = wn * 64 + nt * 8 + 2 * t4;
            float* p0 = out + ((size_t)blk * MR + r0) * DMODEL + cc;
            float* p1 = out + ((size_t)blk * MR + r0 + 8) * DMODEL + cc;
            *reinterpret_cast<float2*>(p0) = make_float2(o[mt][nt][0], o[mt][nt][1]);
            *reinterpret_cast<float2*>(p1) = make_float2(o[mt][nt][2], o[mt][nt][3]);
        }
}

extern "C" void kernel_launch(void* const* d_in, const int* in_sizes, int n_in,
                              void* d_out, int out_size)
{
    const float* x    = (const float*)d_in[0];
    const float* Wqkv = (const float*)d_in[1];
    const float* Wout = (const float*)d_in[2];
    const float* bout = (const float*)d_in[3];
    float* out = (float*)d_out;

    cvt_w_kernel<<<512, 256>>>(Wqkv, Wout);

    cudaFuncSetAttribute(fused_attn_kernel,
                         cudaFuncAttributeMaxDynamicSharedMemorySize, SM_BYTES);
    fused_attn_kernel<<<GRID, 256, SM_BYTES>>>(x, bout, out);
}